// round 2
// baseline (speedup 1.0000x reference)
#include <cuda_runtime.h>

// FocalLoss_53541062312426 — GB300 sm_103a
// Inputs:  d_in[0] classifications [256,16384,2] f32
//          d_in[1] regressions     [256,16384,1] f32
//          d_in[2] annotations     [256,3,16384] f32 (beat, downbeat, beat_times)
// Output:  d_out [2] f32 = (mean cls_loss, mean reg_loss)
//
// Single fused kernel: element sweep at HBM roofline + last-block-done finisher
// (removes the 8.5us second-launch tail seen in R1).

namespace {
constexpr int   B_       = 256;
constexpr int   T_       = 16384;
constexpr int   CHUNKS   = 8;
constexpr int   TCHUNK   = T_ / CHUNKS;       // 2048
constexpr int   NTHREADS = 256;
constexpr int   TPT      = TCHUNK / NTHREADS; // 8
constexpr int   GRID     = B_ * CHUNKS;       // 2048
constexpr float EPS_     = 1e-4f;
constexpr float LN2F     = 0.6931471805599453f;
constexpr float INV_C    = 22050.0f / (16384.0f * 256.0f);
}

// per-(sample,chunk) partials: [cls_sum(lg2 units), num_pos, reg_sum, K]
__device__ float        g_part[GRID * 4];
__device__ unsigned int g_done = 0u;   // reset by finishing block each call

__device__ __forceinline__ float focal_term(float c, bool lab) {
    c = fminf(fmaxf(c, EPS_), 1.0f - EPS_);
    float omc = 1.0f - c;
    float p = lab ? c : omc;      // prob of the true side
    float q = lab ? omc : c;      // (1 - p)
    float a = lab ? 0.25f : 0.75f;
    float q2 = q * q;
    float q5 = q2 * q2 * q;       // (1-p)^5
    return a * q5 * (-__log2f(p));   // lg2 units; *ln2 applied at partial write
}

__global__ void __launch_bounds__(NTHREADS)
loss_fused(const float* __restrict__ cls,
           const float* __restrict__ reg,
           const float* __restrict__ ann,
           float* __restrict__ out)
{
    const int bidx  = blockIdx.x;
    const int b     = bidx >> 3;          // / CHUNKS
    const int chunk = bidx & (CHUNKS - 1);
    const int t0    = chunk * TCHUNK + threadIdx.x * TPT;

    const float* __restrict__ ann0 = ann + (size_t)b * 3 * T_;
    const float* __restrict__ ann1 = ann0 + T_;
    const float* __restrict__ ann2 = ann0 + 2 * T_;
    const float* __restrict__ clsb = cls + (size_t)b * T_ * 2;
    const float* __restrict__ regb = reg + (size_t)b * T_;

    float cacc = 0.0f;   // focal partial (lg2 units)
    float npos = 0.0f;   // original beat count
    float racc = 0.0f;   // regression partial
    float kacc = 0.0f;   // valid anchor count

#pragma unroll
    for (int g = 0; g < TPT / 4; ++g) {
        const int tg = t0 + 4 * g;
        const float4 bv  = *reinterpret_cast<const float4*>(ann0 + tg);
        const float4 dv  = *reinterpret_cast<const float4*>(ann1 + tg);
        const float4 c01 = *reinterpret_cast<const float4*>(clsb + 2 * tg);
        const float4 c23 = *reinterpret_cast<const float4*>(clsb + 2 * tg + 4);

        const float bt[4] = {bv.x, bv.y, bv.z, bv.w};
        const float dn[4] = {dv.x, dv.y, dv.z, dv.w};
        const float cc[8] = {c01.x, c01.y, c01.z, c01.w,
                             c23.x, c23.y, c23.z, c23.w};

#pragma unroll
        for (int j = 0; j < 4; ++j) {
            const int   t    = tg + j;
            const float beat = bt[j];
            const bool  isb  = (beat != 0.0f);
            const bool  isd  = (dn[j] != 0.0f);

            cacc += focal_term(cc[2 * j],     isb &&  isd);  // downbeat class
            cacc += focal_term(cc[2 * j + 1], isb && !isd);  // other-beat class
            npos += beat;

            // anchor mask with last-frame adjustment:
            //   pos[T-2] |= beat[T-1];  pos[T-1] = 0
            float posf = beat;
            if (t >= T_ - 2) {
                const float lastb = ann0[T_ - 1];
                if (t == T_ - 2) {
                    if (lastb != 0.0f) posf = 1.0f;
                } else {            // t == T_-1
                    posf = 0.0f;
                }
            }
            if (posf != 0.0f) {
                const float rn = ann2[t] * INV_C;
                const float d0 = rn - regb[t];
                const float d1 = rn - regb[t + 1];  // t <= T-2 here
                racc += 0.5f * (d0 * d0 + d1 * d1);
                kacc += 1.0f;
            }
        }
    }

    // ---- block reduction ----
    const unsigned lane = threadIdx.x & 31u;
    const unsigned wid  = threadIdx.x >> 5;
#pragma unroll
    for (int o = 16; o > 0; o >>= 1) {
        cacc += __shfl_down_sync(0xffffffffu, cacc, o);
        npos += __shfl_down_sync(0xffffffffu, npos, o);
        racc += __shfl_down_sync(0xffffffffu, racc, o);
        kacc += __shfl_down_sync(0xffffffffu, kacc, o);
    }
    __shared__ float sm[NTHREADS / 32][4];
    __shared__ bool  s_last;
    if (lane == 0) {
        sm[wid][0] = cacc; sm[wid][1] = npos;
        sm[wid][2] = racc; sm[wid][3] = kacc;
    }
    __syncthreads();
    if (threadIdx.x == 0) {
        float c = 0.0f, n = 0.0f, r = 0.0f, k = 0.0f;
#pragma unroll
        for (int w = 0; w < NTHREADS / 32; ++w) {
            c += sm[w][0]; n += sm[w][1]; r += sm[w][2]; k += sm[w][3];
        }
        float* o = &g_part[bidx * 4];
        o[0] = c * LN2F;
        o[1] = n;
        o[2] = r;
        o[3] = k;
        __threadfence();                         // partials visible before count
        unsigned prev = atomicAdd(&g_done, 1u);
        s_last = (prev == (unsigned)(GRID - 1));
    }
    __syncthreads();

    if (!s_last) return;

    // ---- last block: final reduction (partials are L2-hot) ----
    __threadfence();   // acquire side: see all blocks' partials
    {
        const int bb = threadIdx.x;   // one thread per sample
        float cs = 0.0f, np = 0.0f, rs = 0.0f, kk = 0.0f;
#pragma unroll
        for (int ch = 0; ch < CHUNKS; ++ch) {
            const float4 p = *reinterpret_cast<const float4*>(&g_part[(bb * CHUNKS + ch) * 4]);
            cs += p.x; np += p.y; rs += p.z; kk += p.w;
        }
        float cl = cs / np * 10.0f;
        float rl = rs / kk * 10.0f;

        const unsigned l2 = threadIdx.x & 31u;
        const unsigned w2 = threadIdx.x >> 5;
#pragma unroll
        for (int o = 16; o > 0; o >>= 1) {
            cl += __shfl_down_sync(0xffffffffu, cl, o);
            rl += __shfl_down_sync(0xffffffffu, rl, o);
        }
        __shared__ float sc[8], sr[8];
        if (l2 == 0) { sc[w2] = cl; sr[w2] = rl; }
        __syncthreads();
        if (threadIdx.x == 0) {
            float a = 0.0f, r = 0.0f;
#pragma unroll
            for (int w = 0; w < 8; ++w) { a += sc[w]; r += sr[w]; }
            out[0] = a * (1.0f / 256.0f);
            out[1] = r * (1.0f / 256.0f);
            g_done = 0u;          // reset for next graph replay (deterministic)
            __threadfence();
        }
    }
}

extern "C" void kernel_launch(void* const* d_in, const int* in_sizes, int n_in,
                              void* d_out, int out_size) {
    const float* cls = (const float*)d_in[0];
    const float* reg = (const float*)d_in[1];
    const float* ann = (const float*)d_in[2];
    float* out = (float*)d_out;
    (void)in_sizes; (void)n_in; (void)out_size;

    loss_fused<<<GRID, NTHREADS>>>(cls, reg, ann, out);
}